// round 11
// baseline (speedup 1.0000x reference)
#include <cuda_runtime.h>
#include <math.h>

#define F_IN    128
#define HEADS   4
#define CDIM    64
#define HC      256      // HEADS*CDIM
#define HIDDEN  128
#define YDIM    512      // HEADS*F_IN
#define MAXG    1000
#define CAP     256      // per-target edge bin capacity
#define XCAP    64       // rows cached in smem (deg ~Poisson(17), max ~40)
#define NEG_SLOPE 0.2f
#define TB2     8        // targets per block in k_out4
#define KS      8        // k-splits in k_out4 (chunks of 64)
#define CHK     64       // k-chunk width

// ---------------- scratch (static device globals; no allocation) -------------
// g_deg is zero at context start and self-reset by k_agg each run.
__device__ int   g_deg[MAXG];
__device__ int   g_ce_src[MAXG * CAP];    // 1 MB
__device__ float g_wsrc[HEADS][F_IN];     // W_h @ att_src_h
__device__ float g_wdst[HEADS][F_IN];     // W_h @ att_dst_h
__device__ float g_y[MAXG][HEADS][F_IN];  // per-target aggregated x (2 MB)
__device__ float g_M[YDIM][HIDDEN];       // 0.25 * (W_h @ fcW), stacked (256 KB)
__device__ float g_b2[HIDDEN];            // bias @ fcW + fcb

// process one edge: registers only, no arrays (avoid LMEM spill)
__device__ __forceinline__ void edge_try(int src, int dst,
                                         const int* __restrict__ ptr,
                                         const int* __restrict__ tni,
                                         int p0, int pG, int stride, float inv,
                                         int G) {
    if (dst < p0 || dst >= pG) return;
    int g = -1;
    if (stride > 0) {
        int gg = (int)((float)(dst - p0) * inv);
        gg = max(0, min(G - 1, gg));
        if (__ldg(&ptr[gg]) <= dst && dst < __ldg(&ptr[gg + 1]))
            g = gg;
    }
    if (g < 0) {  // fallback: binary search (boundary rounding / nonuniform)
        int lo = 0, hi = G;
        while (hi - lo > 1) {
            int mid = (lo + hi) >> 1;
            if (__ldg(&ptr[mid]) <= dst) lo = mid; else hi = mid;
        }
        g = lo;
    }
    if (__ldg(&ptr[g]) + __ldg(&tni[g]) == dst) {
        int pos = atomicAdd(&g_deg[g], 1);
        if (pos < CAP) g_ce_src[g * CAP + pos] = src;
    }
}

// ---------------- K1: folds (ride free) + edge scan ---------------------------
// blocks: [0] att-fold | [1,256] M-fold | [257] b2 | [258, ...) edge items
__global__ void k_main(const float* __restrict__ W,
                       const float* __restrict__ att_src,
                       const float* __restrict__ att_dst,
                       const float* __restrict__ fcW,
                       const float* __restrict__ bias,
                       const float* __restrict__ fcb,
                       const int* __restrict__ ei,
                       const int* __restrict__ ptr,
                       const int* __restrict__ tni,
                       int E, int G) {
    int bid = blockIdx.x, tid = threadIdx.x;
    if (bid == 0) {
        // g_wsrc[h][k] = sum_c W[k, h*64+c] * att_src[h*64+c]
        int k = tid & 127, half = tid >> 7;
        const float* att = half ? att_dst : att_src;
        float* dstp = half ? &g_wdst[0][0] : &g_wsrc[0][0];
        #pragma unroll
        for (int h = 0; h < HEADS; h++) {
            float a = 0.f;
            #pragma unroll 8
            for (int c = 0; c < CDIM; c++)
                a += W[k * HC + h * CDIM + c] * att[h * CDIM + c];
            dstp[h * F_IN + k] = a;
        }
        return;
    }
    if (bid <= 256) {
        // M[h*128+k][j] = 0.25 * sum_c W[k, h*64+c] * fcW[c*128+j]
        int hk = (bid - 1) * 2 + (tid >> 7);
        int j = tid & 127;
        int h = hk >> 7, k = hk & 127;
        const float* wrow = W + k * HC + h * CDIM;
        float acc = 0.f;
        #pragma unroll 8
        for (int c = 0; c < CDIM; c++)
            acc += __ldg(&wrow[c]) * __ldg(&fcW[c * HIDDEN + j]);
        g_M[hk][j] = 0.25f * acc;
        return;
    }
    if (bid == 257) {
        if (tid < HIDDEN) {
            float b = fcb[tid];
            #pragma unroll 8
            for (int c = 0; c < CDIM; c++)
                b += bias[c] * fcW[c * HIDDEN + tid];
            g_b2[tid] = b;
        }
        return;
    }
    // ---- edge scan (registers only, fully unrolled) ----
    int nE4 = E >> 2;
    int rem = E - (nE4 << 2);
    int item = (bid - 258) * 256 + tid;
    int p0 = __ldg(&ptr[0]);
    int pG = __ldg(&ptr[G]);
    int stride = __ldg(&ptr[1]) - p0;
    float inv = (stride > 0) ? (1.0f / (float)stride) : 0.f;

    if (item < nE4) {
        int4 s4 = __ldg((const int4*)ei + item);
        int4 d4 = __ldg((const int4*)(ei + E) + item);
        edge_try(s4.x, d4.x, ptr, tni, p0, pG, stride, inv, G);
        edge_try(s4.y, d4.y, ptr, tni, p0, pG, stride, inv, G);
        edge_try(s4.z, d4.z, ptr, tni, p0, pG, stride, inv, G);
        edge_try(s4.w, d4.w, ptr, tni, p0, pG, stride, inv, G);
    } else if (item < nE4 + rem) {
        int e = (nE4 << 2) + (item - nE4);
        edge_try(__ldg(&ei[e]), __ldg(&ei[E + e]),
                 ptr, tni, p0, pG, stride, inv, G);
    } else if (item < nE4 + rem + G) {
        int g = item - nE4 - rem;           // self loop of the target node
        int node = __ldg(&ptr[g]) + __ldg(&tni[g]);
        int pos = atomicAdd(&g_deg[g], 1);
        if (pos < CAP) g_ce_src[g * CAP + pos] = node;
    }
}

// ---------------- K2: fused logits + softmax + aggregation (x rows cached) ---
// Also: resets g_deg[t] for the next graph replay, and writes out[t] = b2.
__global__ __launch_bounds__(256)
void k_agg(const float* __restrict__ x,
           const int* __restrict__ ptr,
           const int* __restrict__ tni,
           float* __restrict__ out) {
    int t = blockIdx.x;
    int tid = threadIdx.x;                       // 256 = 8 warps
    int w = tid >> 5, lane = tid & 31;
    __shared__ __align__(16) float s_x[XCAP][F_IN];   // 32 KB row cache
    __shared__ int   s_src[CAP];
    __shared__ float s_v[CAP][HEADS];            // a_src, then alpha
    __shared__ __align__(16) float s_adst[HEADS];
    __shared__ float s_max[HEADS], s_sum[HEADS];

    int deg = min(g_deg[t], CAP);
    int tnode = __ldg(&ptr[t]) + __ldg(&tni[t]);

    for (int e = tid; e < deg; e += 256)
        s_src[e] = g_ce_src[t * CAP + e];
    __syncthreads();
    if (tid == 0) g_deg[t] = 0;                  // self-reset for next replay
    // out init with b2 (k_out4 accumulates on top)
    if (tid < HIDDEN) out[(size_t)t * HIDDEN + tid] = g_b2[tid];

    // warp 0 extra: target's a_dst
    if (w == 0) {
        float4 xv = __ldg((const float4*)(x + (size_t)tnode * F_IN) + lane);
        float d[HEADS];
        #pragma unroll
        for (int h = 0; h < HEADS; h++) {
            float4 wd = *((const float4*)&g_wdst[h][0] + lane);
            d[h] = xv.x * wd.x + xv.y * wd.y + xv.z * wd.z + xv.w * wd.w;
        }
        #pragma unroll
        for (int o = 16; o > 0; o >>= 1)
            #pragma unroll
            for (int h = 0; h < HEADS; h++)
                d[h] += __shfl_xor_sync(0xFFFFFFFFu, d[h], o);
        if (lane == 0)
            *(float4*)s_adst = make_float4(d[0], d[1], d[2], d[3]);
    }
    // all warps: per-edge a_src, 2 edges per warp per round; cache rows in smem
    for (int eb = w * 2; eb < deg; eb += 16) {
        int e1ok = (eb + 1 < deg);
        int src0 = s_src[eb];
        int src1 = e1ok ? s_src[eb + 1] : src0;
        float4 xv0 = __ldg((const float4*)(x + (size_t)src0 * F_IN) + lane);
        float4 xv1 = __ldg((const float4*)(x + (size_t)src1 * F_IN) + lane);
        if (eb < XCAP)
            *((float4*)&s_x[eb][0] + lane) = xv0;
        if (e1ok && eb + 1 < XCAP)
            *((float4*)&s_x[eb + 1][0] + lane) = xv1;
        float s0[HEADS], s1[HEADS];
        #pragma unroll
        for (int h = 0; h < HEADS; h++) {
            float4 ws = *((const float4*)&g_wsrc[h][0] + lane);
            s0[h] = xv0.x * ws.x + xv0.y * ws.y + xv0.z * ws.z + xv0.w * ws.w;
            s1[h] = xv1.x * ws.x + xv1.y * ws.y + xv1.z * ws.z + xv1.w * ws.w;
        }
        #pragma unroll
        for (int o = 16; o > 0; o >>= 1)
            #pragma unroll
            for (int h = 0; h < HEADS; h++) {
                s0[h] += __shfl_xor_sync(0xFFFFFFFFu, s0[h], o);
                s1[h] += __shfl_xor_sync(0xFFFFFFFFu, s1[h], o);
            }
        if (lane == 0) {
            *(float4*)&s_v[eb][0] = make_float4(s0[0], s0[1], s0[2], s0[3]);
            if (e1ok)
                *(float4*)&s_v[eb + 1][0] = make_float4(s1[0], s1[1], s1[2], s1[3]);
        }
    }
    __syncthreads();

    // per-head max + sum of exp (one warp per head)
    if (tid < 128) {
        int h = tid >> 5, l = tid & 31;
        float ad = s_adst[h];
        float m = -INFINITY;
        for (int e = l; e < deg; e += 32) {
            float v = s_v[e][h] + ad;
            v = (v > 0.f) ? v : NEG_SLOPE * v;
            m = fmaxf(m, v);
        }
        #pragma unroll
        for (int o = 16; o > 0; o >>= 1)
            m = fmaxf(m, __shfl_xor_sync(0xFFFFFFFFu, m, o));
        float sm = 0.f;
        for (int e = l; e < deg; e += 32) {
            float v = s_v[e][h] + ad;
            v = (v > 0.f) ? v : NEG_SLOPE * v;
            sm += expf(v - m);
        }
        #pragma unroll
        for (int o = 16; o > 0; o >>= 1)
            sm += __shfl_xor_sync(0xFFFFFFFFu, sm, o);
        if (l == 0) { s_max[h] = m; s_sum[h] = sm; }
    }
    __syncthreads();

    // alpha in place
    for (int e = tid; e < deg; e += 256) {
        #pragma unroll
        for (int h = 0; h < HEADS; h++) {
            float v = s_v[e][h] + s_adst[h];
            v = (v > 0.f) ? v : NEG_SLOPE * v;
            s_v[e][h] = expf(v - s_max[h]) / (s_sum[h] + 1e-16f);
        }
    }
    __syncthreads();

    // y[h][k] = sum_e alpha[e][h] * x_row[e][k]  (rows from smem cache)
    int k = tid & 127, hp = tid >> 7;            // hp: heads {0,1} or {2,3}
    int h0 = hp * 2, h1 = h0 + 1;
    float a0 = 0.f, a1 = 0.f;
    int e = 0;
    int dcap = min(deg, XCAP);
    for (; e + 2 <= dcap; e += 2) {
        float xv0 = s_x[e][k];
        float xv1 = s_x[e + 1][k];
        a0 += s_v[e][h0] * xv0 + s_v[e + 1][h0] * xv1;
        a1 += s_v[e][h1] * xv0 + s_v[e + 1][h1] * xv1;
    }
    for (; e < dcap; e++) {
        float xv = s_x[e][k];
        a0 += s_v[e][h0] * xv;
        a1 += s_v[e][h1] * xv;
    }
    for (; e < deg; e++) {   // overflow fallback (rare)
        float xv = __ldg(&x[(size_t)s_src[e] * F_IN + k]);
        a0 += s_v[e][h0] * xv;
        a1 += s_v[e][h1] * xv;
    }
    g_y[t][h0][k] = a0;
    g_y[t][h1][k] = a1;
}

// ---------------- K3: out += Y @ M  (KS=8 k-split, kg halves, smem reduce) ---
// grid = KS * ceil(G/TB2). blockIdx.x % KS = 64-wide k-chunk.
// 256 threads: j = tid&127, kg = tid>>7 -> 32-k subrange; 8 target accumulators.
__global__ __launch_bounds__(256)
void k_out4(float* __restrict__ out, int G) {
    __shared__ __align__(16) float s_y[TB2][CHK];     // 2 KB k-chunk of y
    __shared__ float s_part[2][TB2][HIDDEN];          // 8 KB partials

    int kc = blockIdx.x % KS;
    int t0 = (blockIdx.x / KS) * TB2;
    if (t0 >= G) return;
    int cnt = min(TB2, G - t0);
    int tid = threadIdx.x;
    int k0 = kc * CHK;

    // load y chunk: rows t0..t0+cnt, cols [k0, k0+64): 8 rows x 16 float4
    if (tid < TB2 * (CHK / 4)) {
        int r = tid >> 4, c4 = tid & 15;
        if (r < cnt)
            *(float4*)&s_y[r][c4 * 4] =
                *(const float4*)(&g_y[t0 + r][0][0] + k0 + c4 * 4);
    }
    __syncthreads();

    int j = tid & 127, kg = tid >> 7;
    int kb = kg * 32;
    float acc[TB2];
    #pragma unroll
    for (int t = 0; t < TB2; t++) acc[t] = 0.f;

    #pragma unroll 4
    for (int kk = 0; kk < 32; kk += 4) {
        int k = k0 + kb + kk;
        float m0 = __ldg(&g_M[k + 0][j]);
        float m1 = __ldg(&g_M[k + 1][j]);
        float m2 = __ldg(&g_M[k + 2][j]);
        float m3 = __ldg(&g_M[k + 3][j]);
        #pragma unroll
        for (int t = 0; t < TB2; t++) {
            float4 yv = *(const float4*)&s_y[t][kb + kk];
            acc[t] += yv.x * m0 + yv.y * m1 + yv.z * m2 + yv.w * m3;
        }
    }
    #pragma unroll
    for (int t = 0; t < TB2; t++) s_part[kg][t][j] = acc[t];
    __syncthreads();

    if (kg == 0) {
        #pragma unroll
        for (int t = 0; t < TB2; t++) {
            if (t < cnt)
                atomicAdd(&out[(size_t)(t0 + t) * HIDDEN + j],
                          s_part[0][t][j] + s_part[1][t][j]);
        }
    }
}

// ---------------- launch ----------------
extern "C" void kernel_launch(void* const* d_in, const int* in_sizes, int n_in,
                              void* d_out, int out_size) {
    const float* x        = (const float*)d_in[0];
    const float* W        = (const float*)d_in[1];
    const float* att_src  = (const float*)d_in[2];
    const float* att_dst  = (const float*)d_in[3];
    const float* bias     = (const float*)d_in[4];
    const float* fc_W     = (const float*)d_in[5];
    const float* fc_b     = (const float*)d_in[6];
    const int*   ei       = (const int*)d_in[7];
    const int*   ptr      = (const int*)d_in[8];
    const int*   tni      = (const int*)d_in[9];
    float*       out      = (float*)d_out;

    int E = in_sizes[7] / 2;           // 800000
    int G = in_sizes[9];               // 1000

    int nE4 = E >> 2, rem = E - (nE4 << 2);
    int items = nE4 + rem + G;
    k_main<<<258 + (items + 255) / 256, 256>>>(W, att_src, att_dst, fc_W,
                                               bias, fc_b, ei, ptr, tni, E, G);
    k_agg<<<G, 256>>>(x, ptr, tni, out);
    k_out4<<<KS * ((G + TB2 - 1) / TB2), 256>>>(out, G);
}

// round 12
// speedup vs baseline: 2.1582x; 2.1582x over previous
#include <cuda_runtime.h>
#include <math.h>

#define F_IN    128
#define HEADS   4
#define CDIM    64
#define HC      256      // HEADS*CDIM
#define HIDDEN  128
#define YDIM    512      // HEADS*F_IN
#define MAXG    1000
#define CAP     256      // per-target edge bin capacity
#define XCAP    64       // rows cached in smem (deg ~Poisson(17), max ~40)
#define NEG_SLOPE 0.2f
#define TB2     8        // targets per block in k_out4
#define KS      8        // k-splits in k_out4 (chunks of 64)
#define CHK     64       // k-chunk width

// ---------------- scratch (static device globals; no allocation) -------------
// g_deg is zero at context start and self-reset by k_agg each run.
__device__ int   g_deg[MAXG];
__device__ int   g_ce_src[MAXG * CAP];    // 1 MB
__device__ float g_wsrc[HEADS][F_IN];     // W_h @ att_src_h
__device__ float g_wdst[HEADS][F_IN];     // W_h @ att_dst_h
__device__ float g_y[MAXG][HEADS][F_IN];  // per-target aggregated x (2 MB)
__device__ float g_M[YDIM][HIDDEN];       // 0.25 * (W_h @ fcW), stacked (256 KB)
__device__ float g_b2[HIDDEN];            // bias @ fcW + fcb

__device__ __forceinline__ float dot4(float4 a, float4 b) {
    return a.x * b.x + a.y * b.y + a.z * b.z + a.w * b.w;
}

// process one edge: registers only
__device__ __forceinline__ void edge_try(int src, int dst,
                                         const int* __restrict__ ptr,
                                         const int* __restrict__ tni,
                                         int p0, int pG, int stride, float inv,
                                         int G) {
    if (dst < p0 || dst >= pG) return;
    int g = -1;
    if (stride > 0) {
        int gg = (int)((float)(dst - p0) * inv);
        gg = max(0, min(G - 1, gg));
        if (__ldg(&ptr[gg]) <= dst && dst < __ldg(&ptr[gg + 1]))
            g = gg;
    }
    if (g < 0) {  // fallback: binary search (boundary rounding / nonuniform)
        int lo = 0, hi = G;
        while (hi - lo > 1) {
            int mid = (lo + hi) >> 1;
            if (__ldg(&ptr[mid]) <= dst) lo = mid; else hi = mid;
        }
        g = lo;
    }
    if (__ldg(&ptr[g]) + __ldg(&tni[g]) == dst) {
        int pos = atomicAdd(&g_deg[g], 1);
        if (pos < CAP) g_ce_src[g * CAP + pos] = src;
    }
}

// ---------------- K1: folds (coalesced) + edge scan ---------------------------
// blocks: [0,16) att-fold (warp-per-k) | [16,272) M-fold | [272] b2
//         | [273, ...) edge items
__global__ void k_main(const float* __restrict__ W,
                       const float* __restrict__ att_src,
                       const float* __restrict__ att_dst,
                       const float* __restrict__ fcW,
                       const float* __restrict__ bias,
                       const float* __restrict__ fcb,
                       const int* __restrict__ ei,
                       const int* __restrict__ ptr,
                       const int* __restrict__ tni,
                       int E, int G) {
    int bid = blockIdx.x, tid = threadIdx.x;
    if (bid < 16) {
        // warp-per-k: coalesced row load of W[k,:], reduce per 64-col head seg.
        int wid = tid >> 5, lane = tid & 31;
        int k = bid * 8 + wid;                 // 16 blocks x 8 warps = 128 k's
        const float4* row = (const float4*)(W + k * HC);
        float4 a = __ldg(row + lane);          // cols [4l, 4l+4): head l/16
        float4 b = __ldg(row + lane + 32);     // cols [128+4l, ..): head 2+l/16
        float4 sa = __ldg((const float4*)att_src + lane);
        float4 sb = __ldg((const float4*)att_src + lane + 32);
        float4 da = __ldg((const float4*)att_dst + lane);
        float4 db = __ldg((const float4*)att_dst + lane + 32);
        float s_lo = dot4(a, sa), s_hi = dot4(b, sb);
        float d_lo = dot4(a, da), d_hi = dot4(b, db);
        #pragma unroll
        for (int o = 8; o > 0; o >>= 1) {      // width=16: head segments
            s_lo += __shfl_down_sync(0xFFFFFFFFu, s_lo, o, 16);
            s_hi += __shfl_down_sync(0xFFFFFFFFu, s_hi, o, 16);
            d_lo += __shfl_down_sync(0xFFFFFFFFu, d_lo, o, 16);
            d_hi += __shfl_down_sync(0xFFFFFFFFu, d_hi, o, 16);
        }
        if ((lane & 15) == 0) {
            int hb = lane >> 4;                // 0 or 1
            g_wsrc[hb][k]     = s_lo;
            g_wsrc[hb + 2][k] = s_hi;
            g_wdst[hb][k]     = d_lo;
            g_wdst[hb + 2][k] = d_hi;
        }
        return;
    }
    if (bid < 272) {
        // M[h*128+k][j] = 0.25 * sum_c W[k, h*64+c] * fcW[c*128+j]
        int hk = (bid - 16) * 2 + (tid >> 7);
        int j = tid & 127;
        int h = hk >> 7, k = hk & 127;
        const float* wrow = W + k * HC + h * CDIM;
        float acc = 0.f;
        #pragma unroll 8
        for (int c = 0; c < CDIM; c++)
            acc += __ldg(&wrow[c]) * __ldg(&fcW[c * HIDDEN + j]);
        g_M[hk][j] = 0.25f * acc;
        return;
    }
    if (bid == 272) {
        if (tid < HIDDEN) {
            float b = fcb[tid];
            #pragma unroll 8
            for (int c = 0; c < CDIM; c++)
                b += bias[c] * fcW[c * HIDDEN + tid];
            g_b2[tid] = b;
        }
        return;
    }
    // ---- edge scan (registers only, fully unrolled) ----
    int nE4 = E >> 2;
    int rem = E - (nE4 << 2);
    int item = (bid - 273) * 256 + tid;
    int p0 = __ldg(&ptr[0]);
    int pG = __ldg(&ptr[G]);
    int stride = __ldg(&ptr[1]) - p0;
    float inv = (stride > 0) ? (1.0f / (float)stride) : 0.f;

    if (item < nE4) {
        int4 s4 = __ldg((const int4*)ei + item);
        int4 d4 = __ldg((const int4*)(ei + E) + item);
        edge_try(s4.x, d4.x, ptr, tni, p0, pG, stride, inv, G);
        edge_try(s4.y, d4.y, ptr, tni, p0, pG, stride, inv, G);
        edge_try(s4.z, d4.z, ptr, tni, p0, pG, stride, inv, G);
        edge_try(s4.w, d4.w, ptr, tni, p0, pG, stride, inv, G);
    } else if (item < nE4 + rem) {
        int e = (nE4 << 2) + (item - nE4);
        edge_try(__ldg(&ei[e]), __ldg(&ei[E + e]),
                 ptr, tni, p0, pG, stride, inv, G);
    } else if (item < nE4 + rem + G) {
        int g = item - nE4 - rem;           // self loop of the target node
        int node = __ldg(&ptr[g]) + __ldg(&tni[g]);
        int pos = atomicAdd(&g_deg[g], 1);
        if (pos < CAP) g_ce_src[g * CAP + pos] = node;
    }
}

// ---------------- K2: fused logits + softmax + aggregation (x rows cached) ---
// Also: resets g_deg[t] for the next graph replay, and writes out[t] = b2.
__global__ __launch_bounds__(256)
void k_agg(const float* __restrict__ x,
           const int* __restrict__ ptr,
           const int* __restrict__ tni,
           float* __restrict__ out) {
    int t = blockIdx.x;
    int tid = threadIdx.x;                       // 256 = 8 warps
    int w = tid >> 5, lane = tid & 31;
    __shared__ __align__(16) float s_x[XCAP][F_IN];   // 32 KB row cache
    __shared__ int   s_src[CAP];
    __shared__ float s_v[CAP][HEADS];            // a_src, then alpha
    __shared__ __align__(16) float s_adst[HEADS];
    __shared__ float s_max[HEADS], s_sum[HEADS];

    int deg = min(g_deg[t], CAP);
    int tnode = __ldg(&ptr[t]) + __ldg(&tni[t]);

    for (int e = tid; e < deg; e += 256)
        s_src[e] = g_ce_src[t * CAP + e];
    __syncthreads();
    if (tid == 0) g_deg[t] = 0;                  // self-reset for next replay
    // out init with b2 (k_out4 accumulates on top)
    if (tid < HIDDEN) out[(size_t)t * HIDDEN + tid] = g_b2[tid];

    // warp 0 extra: target's a_dst
    if (w == 0) {
        float4 xv = __ldg((const float4*)(x + (size_t)tnode * F_IN) + lane);
        float d[HEADS];
        #pragma unroll
        for (int h = 0; h < HEADS; h++) {
            float4 wd = *((const float4*)&g_wdst[h][0] + lane);
            d[h] = xv.x * wd.x + xv.y * wd.y + xv.z * wd.z + xv.w * wd.w;
        }
        #pragma unroll
        for (int o = 16; o > 0; o >>= 1)
            #pragma unroll
            for (int h = 0; h < HEADS; h++)
                d[h] += __shfl_xor_sync(0xFFFFFFFFu, d[h], o);
        if (lane == 0)
            *(float4*)s_adst = make_float4(d[0], d[1], d[2], d[3]);
    }
    // all warps: per-edge a_src, 2 edges per warp per round; cache rows in smem
    for (int eb = w * 2; eb < deg; eb += 16) {
        int e1ok = (eb + 1 < deg);
        int src0 = s_src[eb];
        int src1 = e1ok ? s_src[eb + 1] : src0;
        float4 xv0 = __ldg((const float4*)(x + (size_t)src0 * F_IN) + lane);
        float4 xv1 = __ldg((const float4*)(x + (size_t)src1 * F_IN) + lane);
        if (eb < XCAP)
            *((float4*)&s_x[eb][0] + lane) = xv0;
        if (e1ok && eb + 1 < XCAP)
            *((float4*)&s_x[eb + 1][0] + lane) = xv1;
        float s0[HEADS], s1[HEADS];
        #pragma unroll
        for (int h = 0; h < HEADS; h++) {
            float4 ws = *((const float4*)&g_wsrc[h][0] + lane);
            s0[h] = xv0.x * ws.x + xv0.y * ws.y + xv0.z * ws.z + xv0.w * ws.w;
            s1[h] = xv1.x * ws.x + xv1.y * ws.y + xv1.z * ws.z + xv1.w * ws.w;
        }
        #pragma unroll
        for (int o = 16; o > 0; o >>= 1)
            #pragma unroll
            for (int h = 0; h < HEADS; h++) {
                s0[h] += __shfl_xor_sync(0xFFFFFFFFu, s0[h], o);
                s1[h] += __shfl_xor_sync(0xFFFFFFFFu, s1[h], o);
            }
        if (lane == 0) {
            *(float4*)&s_v[eb][0] = make_float4(s0[0], s0[1], s0[2], s0[3]);
            if (e1ok)
                *(float4*)&s_v[eb + 1][0] = make_float4(s1[0], s1[1], s1[2], s1[3]);
        }
    }
    __syncthreads();

    // per-head max + sum of exp (one warp per head)
    if (tid < 128) {
        int h = tid >> 5, l = tid & 31;
        float ad = s_adst[h];
        float m = -INFINITY;
        for (int e = l; e < deg; e += 32) {
            float v = s_v[e][h] + ad;
            v = (v > 0.f) ? v : NEG_SLOPE * v;
            m = fmaxf(m, v);
        }
        #pragma unroll
        for (int o = 16; o > 0; o >>= 1)
            m = fmaxf(m, __shfl_xor_sync(0xFFFFFFFFu, m, o));
        float sm = 0.f;
        for (int e = l; e < deg; e += 32) {
            float v = s_v[e][h] + ad;
            v = (v > 0.f) ? v : NEG_SLOPE * v;
            sm += expf(v - m);
        }
        #pragma unroll
        for (int o = 16; o > 0; o >>= 1)
            sm += __shfl_xor_sync(0xFFFFFFFFu, sm, o);
        if (l == 0) { s_max[h] = m; s_sum[h] = sm; }
    }
    __syncthreads();

    // alpha in place
    for (int e = tid; e < deg; e += 256) {
        #pragma unroll
        for (int h = 0; h < HEADS; h++) {
            float v = s_v[e][h] + s_adst[h];
            v = (v > 0.f) ? v : NEG_SLOPE * v;
            s_v[e][h] = expf(v - s_max[h]) / (s_sum[h] + 1e-16f);
        }
    }
    __syncthreads();

    // y[h][k] = sum_e alpha[e][h] * x_row[e][k]  (rows from smem cache)
    int k = tid & 127, hp = tid >> 7;            // hp: heads {0,1} or {2,3}
    int h0 = hp * 2, h1 = h0 + 1;
    float a0 = 0.f, a1 = 0.f;
    int e = 0;
    int dcap = min(deg, XCAP);
    for (; e + 2 <= dcap; e += 2) {
        float xv0 = s_x[e][k];
        float xv1 = s_x[e + 1][k];
        a0 += s_v[e][h0] * xv0 + s_v[e + 1][h0] * xv1;
        a1 += s_v[e][h1] * xv0 + s_v[e + 1][h1] * xv1;
    }
    for (; e < dcap; e++) {
        float xv = s_x[e][k];
        a0 += s_v[e][h0] * xv;
        a1 += s_v[e][h1] * xv;
    }
    for (; e < deg; e++) {   // overflow fallback (rare)
        float xv = __ldg(&x[(size_t)s_src[e] * F_IN + k]);
        a0 += s_v[e][h0] * xv;
        a1 += s_v[e][h1] * xv;
    }
    g_y[t][h0][k] = a0;
    g_y[t][h1][k] = a1;
}

// ---------------- K3: out += Y @ M  (KS=8 k-split, kg halves, smem reduce) ---
__global__ __launch_bounds__(256)
void k_out4(float* __restrict__ out, int G) {
    __shared__ __align__(16) float s_y[TB2][CHK];     // 2 KB k-chunk of y
    __shared__ float s_part[2][TB2][HIDDEN];          // 8 KB partials

    int kc = blockIdx.x % KS;
    int t0 = (blockIdx.x / KS) * TB2;
    if (t0 >= G) return;
    int cnt = min(TB2, G - t0);
    int tid = threadIdx.x;
    int k0 = kc * CHK;

    // load y chunk: rows t0..t0+cnt, cols [k0, k0+64): 8 rows x 16 float4
    if (tid < TB2 * (CHK / 4)) {
        int r = tid >> 4, c4 = tid & 15;
        if (r < cnt)
            *(float4*)&s_y[r][c4 * 4] =
                *(const float4*)(&g_y[t0 + r][0][0] + k0 + c4 * 4);
    }
    __syncthreads();

    int j = tid & 127, kg = tid >> 7;
    int kb = kg * 32;
    float acc[TB2];
    #pragma unroll
    for (int t = 0; t < TB2; t++) acc[t] = 0.f;

    #pragma unroll 4
    for (int kk = 0; kk < 32; kk += 4) {
        int k = k0 + kb + kk;
        float m0 = __ldg(&g_M[k + 0][j]);
        float m1 = __ldg(&g_M[k + 1][j]);
        float m2 = __ldg(&g_M[k + 2][j]);
        float m3 = __ldg(&g_M[k + 3][j]);
        #pragma unroll
        for (int t = 0; t < TB2; t++) {
            float4 yv = *(const float4*)&s_y[t][kb + kk];
            acc[t] += yv.x * m0 + yv.y * m1 + yv.z * m2 + yv.w * m3;
        }
    }
    #pragma unroll
    for (int t = 0; t < TB2; t++) s_part[kg][t][j] = acc[t];
    __syncthreads();

    if (kg == 0) {
        #pragma unroll
        for (int t = 0; t < TB2; t++) {
            if (t < cnt)
                atomicAdd(&out[(size_t)(t0 + t) * HIDDEN + j],
                          s_part[0][t][j] + s_part[1][t][j]);
        }
    }
}

// ---------------- launch ----------------
extern "C" void kernel_launch(void* const* d_in, const int* in_sizes, int n_in,
                              void* d_out, int out_size) {
    const float* x        = (const float*)d_in[0];
    const float* W        = (const float*)d_in[1];
    const float* att_src  = (const float*)d_in[2];
    const float* att_dst  = (const float*)d_in[3];
    const float* bias     = (const float*)d_in[4];
    const float* fc_W     = (const float*)d_in[5];
    const float* fc_b     = (const float*)d_in[6];
    const int*   ei       = (const int*)d_in[7];
    const int*   ptr      = (const int*)d_in[8];
    const int*   tni      = (const int*)d_in[9];
    float*       out      = (float*)d_out;

    int E = in_sizes[7] / 2;           // 800000
    int G = in_sizes[9];               // 1000

    int nE4 = E >> 2, rem = E - (nE4 << 2);
    int items = nE4 + rem + G;
    k_main<<<273 + (items + 255) / 256, 256>>>(W, att_src, att_dst, fc_W,
                                               bias, fc_b, ei, ptr, tni, E, G);
    k_agg<<<G, 256>>>(x, ptr, tni, out);
    k_out4<<<KS * ((G + TB2 - 1) / TB2), 256>>>(out, G);
}